// round 1
// baseline (speedup 1.0000x reference)
#include <cuda_runtime.h>

// ---------------- problem constants ----------------
#define G8      8
#define DK8     8
#define DV16    16
#define CIN64   64
#define H48     48
#define B2304   2304
#define P110592 110592      // B * H
#define NOUT    256         // 192 kv rows + 64 q rows
#define RELW    95          // 2K-1
#define EPS     1e-5f

// ---------------- scratch (device globals; no allocation allowed) ----------------
__device__ float  g_Q  [G8*DK8*H48*B2304];   // [(g*8+c)*48+h][b]  raw projection
__device__ float  g_Kb [G8*DK8*H48*B2304];
__device__ float  g_Vb [G8*DV16*H48*B2304];
__device__ float  g_SV [B2304*G8*DV16*H48];  // [b][(g*16+c)*48+i]  (f_sv applied, pre out-BN)
__device__ float  g_SVE[B2304*G8*DV16*H48];
__device__ double g_projstats[NOUT*2];       // per projection channel: sum, sumsq
__device__ float  g_pa[NOUT], g_pb[NOUT];    // fused BN affine for projections
__device__ double g_simstats[G8*6];          // per g: qk(sum,sq) qr(sum,sq) kr(sum,sq)
__device__ float  g_simco[G8*4];             // a_qk, a_qr(*f_qr), a_kr(*f_kr), shift
__device__ double g_outstats[NOUT*2];        // per out channel o=(g*16+c)*2+side: sum,sumsq
__device__ float  g_oA[NOUT], g_oC[NOUT];

// ---------------- zero stats ----------------
__global__ void k_zero() {
    int t = blockIdx.x * blockDim.x + threadIdx.x;
    if (t < NOUT*2) g_projstats[t] = 0.0;
    if (t < G8*6)   g_simstats[t]  = 0.0;
    if (t < NOUT*2) g_outstats[t]  = 0.0;
}

// ---------------- projection: y = W x  (raw), plus channel stats ----------------
__global__ __launch_bounds__(256)
void k_proj(const float* __restrict__ x,
            const float* __restrict__ Wkv,
            const float* __restrict__ Wq) {
    extern __shared__ float Wsh[];   // 256*64 floats = 64KB
    int tid = threadIdx.x;
    for (int i = tid; i < 192*64; i += 256) Wsh[i] = Wkv[i];
    for (int i = tid; i < 64*64;  i += 256) Wsh[192*64 + i] = Wq[i];
    __syncthreads();

    int s = blockIdx.x * 256 + tid;          // position in [0, 110592)
    int h = s / B2304;
    int b = s - h * B2304;

    float xr[64];
#pragma unroll
    for (int c = 0; c < 64; c++) xr[c] = x[c * P110592 + s];

    for (int o = 0; o < NOUT; o++) {
        const float* w = &Wsh[o * 64];
        float acc = 0.f;
#pragma unroll
        for (int c = 0; c < 64; c++) acc = fmaf(w[c], xr[c], acc);

        float* dst;
        if (o < 192) {
            int g = o / 24, cc = o - g * 24;
            if (cc < 8) dst = &g_Kb[((g*8 + cc)       * H48 + h) * B2304 + b];
            else        dst = &g_Vb[((g*16 + (cc-8))  * H48 + h) * B2304 + b];
        } else {
            int o2 = o - 192;
            int g = o2 >> 3, c = o2 & 7;
            dst = &g_Q[((g*8 + c) * H48 + h) * B2304 + b];
        }
        *dst = acc;

        // warp-reduce stats for this channel
        float s1 = acc, s2 = acc * acc;
#pragma unroll
        for (int off = 16; off; off >>= 1) {
            s1 += __shfl_xor_sync(0xffffffffu, s1, off);
            s2 += __shfl_xor_sync(0xffffffffu, s2, off);
        }
        if ((tid & 31) == 0) {
            atomicAdd(&g_projstats[2*o],   (double)s1);
            atomicAdd(&g_projstats[2*o+1], (double)s2);
        }
    }
}

// ---------------- fold projection BN into affine ----------------
__global__ void k_paffine(const float* __restrict__ gkv, const float* __restrict__ bkv,
                          const float* __restrict__ gq,  const float* __restrict__ bq) {
    int o = threadIdx.x;   // 256
    double s1 = g_projstats[2*o], s2 = g_projstats[2*o+1];
    double mean = s1 / (double)P110592;
    double var  = s2 / (double)P110592 - mean * mean;
    float inv = rsqrtf((float)var + EPS);
    float gg, bb;
    if (o < 192) { gg = gkv[o]; bb = bkv[o]; }
    else         { gg = gq[o-192]; bb = bq[o-192]; }
    float a = gg * inv;
    g_pa[o] = a;
    g_pb[o] = bb - a * (float)mean;
}

// ---------------- sim stats: qk/qr/kr mean & sumsq per g ----------------
#define SS_SMEM ((6528 + 6528 + 8*RELW + 8*RELW) * 4)
__global__ __launch_bounds__(256)
void k_simstats(const float* __restrict__ rel,
                const float* __restrict__ fqr, const float* __restrict__ fkr) {
    extern __shared__ float sm[];
    float* Qs   = sm;                 // 8*48*17 = 6528
    float* Ks   = Qs + 6528;          // 6528
    float* relq = Ks + 6528;          // 8*95
    float* relk = relq + 8*RELW;      // 8*95
    __shared__ double red[6];

    int tid = threadIdx.x;
    int g   = blockIdx.y;
    int b0  = blockIdx.x * 16;

    for (int i = tid; i < 16*RELW; i += 256) {
        if (i < 8*RELW) relq[i] = rel[i];
        else            relk[i - 8*RELW] = rel[i];
    }
    for (int idx = tid; idx < 384*16; idx += 256) {
        int row = idx >> 4, bl = idx & 15;
        int c = row / 48;
        int oq = 192 + g*8 + c;
        int ok = g*24 + c;
        Qs[row*17 + bl] = g_pa[oq] * g_Q [(g*384 + row) * B2304 + b0 + bl] + g_pb[oq];
        Ks[row*17 + bl] = g_pa[ok] * g_Kb[(g*384 + row) * B2304 + b0 + bl] + g_pb[ok];
    }
    if (tid < 6) red[tid] = 0.0;
    __syncthreads();

    float fq = *fqr, fk = *fkr;
    float a0=0,a1=0,a2=0,a3=0,a4=0,a5=0;
    for (int bl = 0; bl < 16; bl++) {
        for (int p = tid; p < 2304; p += 256) {
            int i = p / 48, j = p - (p/48)*48;
            int dq = i - j + 47, dk2 = j - i + 47;
            float qk = 0.f, qr = 0.f, kr = 0.f;
#pragma unroll
            for (int c = 0; c < 8; c++) {
                float qv = Qs[(c*48 + i)*17 + bl];
                float kv = Ks[(c*48 + j)*17 + bl];
                qk = fmaf(qv, kv, qk);
                qr = fmaf(qv, relq[c*RELW + dq],  qr);
                kr = fmaf(kv, relk[c*RELW + dk2], kr);
            }
            qr *= fq; kr *= fk;
            a0 += qk; a1 += qk*qk;
            a2 += qr; a3 += qr*qr;
            a4 += kr; a5 += kr*kr;
        }
    }
    atomicAdd(&red[0], (double)a0); atomicAdd(&red[1], (double)a1);
    atomicAdd(&red[2], (double)a2); atomicAdd(&red[3], (double)a3);
    atomicAdd(&red[4], (double)a4); atomicAdd(&red[5], (double)a5);
    __syncthreads();
    if (tid == 0) {
#pragma unroll
        for (int t = 0; t < 6; t++) atomicAdd(&g_simstats[g*6 + t], red[t]);
    }
}

// ---------------- sim BN -> combine coefficients per g ----------------
__global__ void k_simco(const float* __restrict__ gsim, const float* __restrict__ bsim,
                        const float* __restrict__ fqr,  const float* __restrict__ fkr) {
    int g = threadIdx.x;
    if (g >= G8) return;
    double N = (double)B2304 * 48.0 * 48.0;
    float f[3] = {1.f, *fqr, *fkr};
    float shift = 0.f;
    float a[3];
#pragma unroll
    for (int t = 0; t < 3; t++) {
        double s1 = g_simstats[g*6 + t*2], s2 = g_simstats[g*6 + t*2 + 1];
        double mean = s1 / N, var = s2 / N - mean * mean;
        float inv = rsqrtf((float)var + EPS);
        float aa = gsim[t*G8 + g] * inv;
        shift += bsim[t*G8 + g] - aa * (float)mean;
        a[t] = aa * f[t];    // fold f so the attention kernel uses raw dot products
    }
    g_simco[g*4+0] = a[0];
    g_simco[g*4+1] = a[1];
    g_simco[g*4+2] = a[2];
    g_simco[g*4+3] = shift;
}

// ---------------- attention: logits -> softmax -> sv/sve (+ out stats) ----------------
// smem floats: Qs 6528 + Ks 6528 + Vs 13056 + sim 48*49 + relq 760 + relk 760 + relv 1520
#define AT_SMEM ((6528 + 6528 + 13056 + 48*49 + 8*RELW + 8*RELW + 16*RELW) * 4)
__global__ __launch_bounds__(256)
void k_attn(const float* __restrict__ rel,
            const float* __restrict__ fsv, const float* __restrict__ fsve) {
    extern __shared__ float sm[];
    float* Qs   = sm;                    // 6528
    float* Ks   = Qs + 6528;             // 6528
    float* Vs   = Ks + 6528;             // 16*48*17 = 13056
    float* sim  = Vs + 13056;            // 48*49 = 2352
    float* relq = sim + 48*49;           // 760
    float* relk = relq + 8*RELW;         // 760
    float* relv = relk + 8*RELW;         // 1520
    __shared__ double red[64];           // 16 c * 4 stats

    int tid = threadIdx.x;
    int g   = blockIdx.y;
    int b0  = blockIdx.x * 16;

    for (int i = tid; i < 32*RELW; i += 256) {
        if      (i <  8*RELW) relq[i]            = rel[i];
        else if (i < 16*RELW) relk[i -  8*RELW]  = rel[i];
        else                  relv[i - 16*RELW]  = rel[i];
    }
    for (int idx = tid; idx < 384*16; idx += 256) {
        int row = idx >> 4, bl = idx & 15;
        int c = row / 48;
        int oq = 192 + g*8 + c;
        int ok = g*24 + c;
        Qs[row*17 + bl] = g_pa[oq] * g_Q [(g*384 + row) * B2304 + b0 + bl] + g_pb[oq];
        Ks[row*17 + bl] = g_pa[ok] * g_Kb[(g*384 + row) * B2304 + b0 + bl] + g_pb[ok];
    }
    for (int idx = tid; idx < 768*16; idx += 256) {
        int row = idx >> 4, bl = idx & 15;
        int c = row / 48;
        int ov = g*24 + 8 + c;
        Vs[row*17 + bl] = g_pa[ov] * g_Vb[(g*768 + row) * B2304 + b0 + bl] + g_pb[ov];
    }
    for (int i = tid; i < 64; i += 256) red[i] = 0.0;
    __syncthreads();

    float A0 = g_simco[g*4+0], A1 = g_simco[g*4+1];
    float A2 = g_simco[g*4+2], SH = g_simco[g*4+3];
    float vsv = *fsv, vsve = *fsve;

    float lsv_s[3]  = {0,0,0}, lsv_q[3]  = {0,0,0};
    float lsve_s[3] = {0,0,0}, lsve_q[3] = {0,0,0};

    for (int bl = 0; bl < 16; bl++) {
        // logits
        for (int p = tid; p < 2304; p += 256) {
            int i = p / 48, j = p - (p/48)*48;
            int dq = i - j + 47, dk2 = j - i + 47;
            float qk = 0.f, qr = 0.f, kr = 0.f;
#pragma unroll
            for (int c = 0; c < 8; c++) {
                float qv = Qs[(c*48 + i)*17 + bl];
                float kv = Ks[(c*48 + j)*17 + bl];
                qk = fmaf(qv, kv, qk);
                qr = fmaf(qv, relq[c*RELW + dq],  qr);
                kr = fmaf(kv, relk[c*RELW + dk2], kr);
            }
            sim[i*49 + j] = A0*qk + A1*qr + A2*kr + SH;
        }
        __syncthreads();
        // softmax per row
        if (tid < 48) {
            float mx = -1e30f;
#pragma unroll 4
            for (int j = 0; j < 48; j++) mx = fmaxf(mx, sim[tid*49 + j]);
            float ssum = 0.f;
#pragma unroll 4
            for (int j = 0; j < 48; j++) {
                float e = __expf(sim[tid*49 + j] - mx);
                sim[tid*49 + j] = e;
                ssum += e;
            }
            float r = 1.f / ssum;
#pragma unroll 4
            for (int j = 0; j < 48; j++) sim[tid*49 + j] *= r;
        }
        __syncthreads();
        // sv / sve
        int b = b0 + bl;
#pragma unroll
        for (int k = 0; k < 3; k++) {
            int p = tid + k*256;              // < 768
            int c = p / 48, i = p - (p/48)*48;
            float sv = 0.f, sve = 0.f;
#pragma unroll 8
            for (int j = 0; j < 48; j++) {
                float sj = sim[i*49 + j];
                sv  = fmaf(sj, Vs[(c*48 + j)*17 + bl], sv);
                sve = fmaf(sj, relv[c*RELW + (i - j + 47)], sve);
            }
            sv *= vsv; sve *= vsve;
            g_SV [b*6144 + g*768 + p] = sv;
            g_SVE[b*6144 + g*768 + p] = sve;
            lsv_s[k]  += sv;  lsv_q[k]  += sv*sv;
            lsve_s[k] += sve; lsve_q[k] += sve*sve;
        }
        __syncthreads();
    }
    // block-reduce out stats
#pragma unroll
    for (int k = 0; k < 3; k++) {
        int c = (tid + k*256) / 48;
        atomicAdd(&red[c*4+0], (double)lsv_s[k]);
        atomicAdd(&red[c*4+1], (double)lsv_q[k]);
        atomicAdd(&red[c*4+2], (double)lsve_s[k]);
        atomicAdd(&red[c*4+3], (double)lsve_q[k]);
    }
    __syncthreads();
    if (tid < 16) {
        int o_sv  = (g*16 + tid)*2;
        int o_sve = o_sv + 1;
        atomicAdd(&g_outstats[o_sv*2+0],  red[tid*4+0]);
        atomicAdd(&g_outstats[o_sv*2+1],  red[tid*4+1]);
        atomicAdd(&g_outstats[o_sve*2+0], red[tid*4+2]);
        atomicAdd(&g_outstats[o_sve*2+1], red[tid*4+3]);
    }
}

// ---------------- out BN coefficients ----------------
__global__ void k_outco(const float* __restrict__ gout, const float* __restrict__ bout) {
    int o = threadIdx.x;    // 256
    double N = (double)P110592;
    double s1 = g_outstats[2*o], s2 = g_outstats[2*o+1];
    double mean = s1 / N, var = s2 / N - mean * mean;
    float inv = rsqrtf((float)var + EPS);
    float A = gout[o] * inv;
    g_oA[o] = A;
    g_oC[o] = bout[o] - A * (float)mean;
}

// ---------------- final: affine-combine + transpose [b][r] -> [r][b] ----------------
__global__ __launch_bounds__(256)
void k_final(float* __restrict__ out) {
    __shared__ float tile[32][33];
    int r0 = blockIdx.x * 32;     // r in [0, 6144)
    int b0 = blockIdx.y * 32;     // b in [0, 2304)
    int tx = threadIdx.x, ty = threadIdx.y;   // (32, 8)

    int r = r0 + tx;
    int gc = r / 48;
    float Asv  = g_oA[gc*2],   Csv  = g_oC[gc*2];
    float Asve = g_oA[gc*2+1], Csve = g_oC[gc*2+1];
#pragma unroll
    for (int k = 0; k < 4; k++) {
        int b = b0 + ty + k*8;
        float v = Asv * g_SV[b*6144 + r] + Csv
                + Asve * g_SVE[b*6144 + r] + Csve;
        tile[ty + k*8][tx] = v;
    }
    __syncthreads();
#pragma unroll
    for (int k = 0; k < 4; k++) {
        int rr = r0 + ty + k*8;
        out[rr * B2304 + b0 + tx] = tile[tx][ty + k*8];
    }
}

// ---------------- launch ----------------
extern "C" void kernel_launch(void* const* d_in, const int* in_sizes, int n_in,
                              void* d_out, int out_size) {
    const float* x    = (const float*)d_in[0];
    const float* Wkv  = (const float*)d_in[1];
    const float* Wq   = (const float*)d_in[2];
    const float* gkv  = (const float*)d_in[3];
    const float* bkv  = (const float*)d_in[4];
    const float* gq   = (const float*)d_in[5];
    const float* bq   = (const float*)d_in[6];
    const float* gsim = (const float*)d_in[7];
    const float* bsim = (const float*)d_in[8];
    const float* gout = (const float*)d_in[9];
    const float* bout = (const float*)d_in[10];
    const float* rel  = (const float*)d_in[11];
    const float* fqr  = (const float*)d_in[12];
    const float* fkr  = (const float*)d_in[13];
    const float* fsv  = (const float*)d_in[14];
    const float* fsve = (const float*)d_in[15];
    float* out = (float*)d_out;

    cudaFuncSetAttribute(k_proj,     cudaFuncAttributeMaxDynamicSharedMemorySize, 65536);
    cudaFuncSetAttribute(k_simstats, cudaFuncAttributeMaxDynamicSharedMemorySize, SS_SMEM);
    cudaFuncSetAttribute(k_attn,     cudaFuncAttributeMaxDynamicSharedMemorySize, AT_SMEM);

    k_zero<<<1, 512>>>();
    k_proj<<<P110592/256, 256, 65536>>>(x, Wkv, Wq);
    k_paffine<<<1, 256>>>(gkv, bkv, gq, bq);
    k_simstats<<<dim3(B2304/16, G8), 256, SS_SMEM>>>(rel, fqr, fkr);
    k_simco<<<1, 32>>>(gsim, bsim, fqr, fkr);
    k_attn<<<dim3(B2304/16, G8), 256, AT_SMEM>>>(rel, fsv, fsve);
    k_outco<<<1, 256>>>(gout, bout);
    k_final<<<dim3(6144/32, B2304/32), dim3(32, 8)>>>(out);
}

// round 3
// speedup vs baseline: 1.3368x; 1.3368x over previous
#include <cuda_runtime.h>

// ---------------- problem constants ----------------
#define G8      8
#define DK8     8
#define DV16    16
#define CIN64   64
#define H48     48
#define B2304   2304
#define P110592 110592      // B * H
#define NOUT    256         // 192 kv rows + 64 q rows
#define RELW    95          // 2K-1
#define EPS     1e-5f

// ---------------- scratch (device globals; no allocation allowed) ----------------
__device__ float  g_Q  [G8*DK8*H48*B2304];   // [(g*8+c)*48+h][b]  raw projection
__device__ float  g_Kb [G8*DK8*H48*B2304];
__device__ float  g_Vb [G8*DV16*H48*B2304];
__device__ float  g_SV [B2304*G8*DV16*H48];  // [b][(g*16+c)*48+i]
__device__ float  g_SVE[B2304*G8*DV16*H48];
__device__ double g_projstats[NOUT*2];
__device__ float  g_pa[NOUT], g_pb[NOUT];
__device__ float  g_simco[G8*4];             // a_qk, a_qr(*f_qr), a_kr(*f_kr), shift
__device__ double g_outstats[NOUT*2];
__device__ float  g_oA[NOUT], g_oC[NOUT];

// analytic sim-stats accumulators
__device__ float  g_SqTot[G8][8][48];        // sum_b q[b,c,i]
__device__ float  g_SkTot[G8][8][48];
__device__ float  g_PqTot[G8][36][48];       // sum_b q[b,c,i]*q[b,c',i]  (c<=c')
__device__ float  g_PkTot[G8][36][48];
__device__ double g_qkstat[G8][2];           // sum qk, sum qk^2

__device__ __forceinline__ void pair_cc(int p, int& c, int& c2) {
    int base = 0, cc = 0;
#pragma unroll
    for (int r = 0; r < 8; r++) {
        int cnt = 8 - r;
        if (p < base + cnt) { cc = r; break; }
        base += cnt;
    }
    c = cc; c2 = cc + (p - base);
}

// ---------------- zero stats ----------------
__global__ void k_zero() {
    int t = blockIdx.x * blockDim.x + threadIdx.x;
    if (t < NOUT*2) g_projstats[t] = 0.0;
    if (t < NOUT*2) g_outstats[t]  = 0.0;
    if (t < G8*2)   ((double*)g_qkstat)[t] = 0.0;
    // float accumulators: 8*(384 + 1728)*2 = 33792 floats
    float* fs = &g_SqTot[0][0][0];   // contiguous? not guaranteed across arrays
    (void)fs;
    int total = G8*8*48;
    for (int i = t; i < total; i += gridDim.x * blockDim.x) {
        (&g_SqTot[0][0][0])[i] = 0.f;
        (&g_SkTot[0][0][0])[i] = 0.f;
    }
    int totalp = G8*36*48;
    for (int i = t; i < totalp; i += gridDim.x * blockDim.x) {
        (&g_PqTot[0][0][0])[i] = 0.f;
        (&g_PkTot[0][0][0])[i] = 0.f;
    }
}

// ---------------- projection: y = W x  (raw), plus channel stats ----------------
__global__ __launch_bounds__(256)
void k_proj(const float* __restrict__ x,
            const float* __restrict__ Wkv,
            const float* __restrict__ Wq) {
    extern __shared__ float Wsh[];   // 256*64 floats = 64KB
    int tid = threadIdx.x;
    for (int i = tid; i < 192*64; i += 256) Wsh[i] = Wkv[i];
    for (int i = tid; i < 64*64;  i += 256) Wsh[192*64 + i] = Wq[i];
    __syncthreads();

    int s = blockIdx.x * 256 + tid;
    int h = s / B2304;
    int b = s - h * B2304;

    float xr[64];
#pragma unroll
    for (int c = 0; c < 64; c++) xr[c] = x[c * P110592 + s];

    for (int o = 0; o < NOUT; o++) {
        const float* w = &Wsh[o * 64];
        float acc = 0.f;
#pragma unroll
        for (int c = 0; c < 64; c++) acc = fmaf(w[c], xr[c], acc);

        float* dst;
        if (o < 192) {
            int g = o / 24, cc = o - g * 24;
            if (cc < 8) dst = &g_Kb[((g*8 + cc)       * H48 + h) * B2304 + b];
            else        dst = &g_Vb[((g*16 + (cc-8))  * H48 + h) * B2304 + b];
        } else {
            int o2 = o - 192;
            int g = o2 >> 3, c = o2 & 7;
            dst = &g_Q[((g*8 + c) * H48 + h) * B2304 + b];
        }
        *dst = acc;

        float s1 = acc, s2 = acc * acc;
#pragma unroll
        for (int off = 16; off; off >>= 1) {
            s1 += __shfl_xor_sync(0xffffffffu, s1, off);
            s2 += __shfl_xor_sync(0xffffffffu, s2, off);
        }
        if ((tid & 31) == 0) {
            atomicAdd(&g_projstats[2*o],   (double)s1);
            atomicAdd(&g_projstats[2*o+1], (double)s2);
        }
    }
}

// ---------------- fold projection BN into affine ----------------
__global__ void k_paffine(const float* __restrict__ gkv, const float* __restrict__ bkv,
                          const float* __restrict__ gq,  const float* __restrict__ bq) {
    int o = threadIdx.x;   // 256
    double s1 = g_projstats[2*o], s2 = g_projstats[2*o+1];
    double mean = s1 / (double)P110592;
    double var  = s2 / (double)P110592 - mean * mean;
    float inv = rsqrtf((float)var + EPS);
    float gg, bb;
    if (o < 192) { gg = gkv[o]; bb = bkv[o]; }
    else         { gg = gq[o-192]; bb = bq[o-192]; }
    float a = gg * inv;
    g_pa[o] = a;
    g_pb[o] = bb - a * (float)mean;
}

// ---------------- analytic sim stats: moments of post-BN q/k ----------------
#define ST_SMEM ((6528 + 6528) * 4)
__global__ __launch_bounds__(256)
void k_stats() {
    extern __shared__ float sm[];
    float* Qs = sm;                 // 8*48*17 = 6528
    float* Ks = Qs + 6528;          // 6528
    __shared__ double sred[2];

    int tid = threadIdx.x;
    int g   = blockIdx.y;
    int b0  = blockIdx.x * 16;

    for (int idx = tid; idx < 384*16; idx += 256) {
        int row = idx >> 4, bl = idx & 15;
        int c = row / 48;
        int oq = 192 + g*8 + c;
        int ok = g*24 + c;
        Qs[row*17 + bl] = g_pa[oq] * g_Q [(g*384 + row) * B2304 + b0 + bl] + g_pb[oq];
        Ks[row*17 + bl] = g_pa[ok] * g_Kb[(g*384 + row) * B2304 + b0 + bl] + g_pb[ok];
    }
    if (tid < 2) sred[tid] = 0.0;
    __syncthreads();

    // qk scalars: per-b Gram pairing + rowsum products
    float lsum = 0.f, lsq = 0.f;
    for (int item = tid; item < 576; item += 256) {        // (pair, bl)
        int p = item >> 4, bl = item & 15;
        int c, c2; pair_cc(p, c, c2);
        float gq = 0.f, gk = 0.f;
#pragma unroll 8
        for (int i = 0; i < 48; i++) {
            gq = fmaf(Qs[(c*48+i)*17+bl], Qs[(c2*48+i)*17+bl], gq);
            gk = fmaf(Ks[(c*48+i)*17+bl], Ks[(c2*48+i)*17+bl], gk);
        }
        float w = (c == c2) ? 1.f : 2.f;
        lsq = fmaf(w * gq, gk, lsq);
    }
    for (int item = tid; item < 128; item += 256) {        // (c, bl)
        int c = item >> 4, bl = item & 15;
        float rq = 0.f, rk = 0.f;
#pragma unroll 8
        for (int i = 0; i < 48; i++) {
            rq += Qs[(c*48+i)*17+bl];
            rk += Ks[(c*48+i)*17+bl];
        }
        lsum = fmaf(rq, rk, lsum);
    }
    atomicAdd(&sred[0], (double)lsum);
    atomicAdd(&sred[1], (double)lsq);

    // per-position first moments
    for (int item = tid; item < 384; item += 256) {
        int c = item / 48, i = item - (item/48)*48;
        float sq = 0.f, sk = 0.f;
#pragma unroll
        for (int bl = 0; bl < 16; bl++) {
            sq += Qs[(c*48+i)*17+bl];
            sk += Ks[(c*48+i)*17+bl];
        }
        atomicAdd(&g_SqTot[g][c][i], sq);
        atomicAdd(&g_SkTot[g][c][i], sk);
    }
    // per-position second cross-moments
    for (int item = tid; item < 1728; item += 256) {
        int p = item / 48, i = item - (item/48)*48;
        int c, c2; pair_cc(p, c, c2);
        float sq = 0.f, sk = 0.f;
#pragma unroll
        for (int bl = 0; bl < 16; bl++) {
            sq = fmaf(Qs[(c*48+i)*17+bl], Qs[(c2*48+i)*17+bl], sq);
            sk = fmaf(Ks[(c*48+i)*17+bl], Ks[(c2*48+i)*17+bl], sk);
        }
        atomicAdd(&g_PqTot[g][p][i], sq);
        atomicAdd(&g_PkTot[g][p][i], sk);
    }
    __syncthreads();
    if (tid == 0) {
        atomicAdd(&g_qkstat[g][0], sred[0]);
        atomicAdd(&g_qkstat[g][1], sred[1]);
    }
}

// ---------------- finalize sim BN coefficients ----------------
__global__ __launch_bounds__(256)
void k_simfin(const float* __restrict__ rel,
              const float* __restrict__ gsim, const float* __restrict__ bsim,
              const float* __restrict__ fqr,  const float* __restrict__ fkr) {
    __shared__ float relq_s[8*RELW], relk_s[8*RELW];
    __shared__ float Rq[384], Rk[384];
    __shared__ float ERq[1728], ERk[1728];
    __shared__ double warp_out[8][4];

    int tid = threadIdx.x;
    for (int i = tid; i < 16*RELW; i += 256) {
        if (i < 8*RELW) relq_s[i] = rel[i];
        else            relk_s[i - 8*RELW] = rel[i];
    }
    __syncthreads();

    for (int it = tid; it < 384; it += 256) {
        int c = it / 48, i = it - (it/48)*48;
        float s = 0.f, sk = 0.f;
#pragma unroll 8
        for (int d = 0; d < 48; d++) {
            s  += relq_s[c*RELW + i + d];
            sk += relk_s[c*RELW + i + d];
        }
        Rq[it] = s; Rk[it] = sk;
    }
    for (int it = tid; it < 1728; it += 256) {
        int p = it / 48, i = it - (it/48)*48;
        int c, c2; pair_cc(p, c, c2);
        float s = 0.f, sk = 0.f;
#pragma unroll 8
        for (int d = 0; d < 48; d++) {
            s  = fmaf(relq_s[c*RELW + i + d], relq_s[c2*RELW + i + d], s);
            sk = fmaf(relk_s[c*RELW + i + d], relk_s[c2*RELW + i + d], sk);
        }
        ERq[it] = s; ERk[it] = sk;
    }
    __syncthreads();

    int w = tid >> 5, lane = tid & 31;   // warp w handles group g = w
    int g = w;
    double qr_s = 0.0, qr_q = 0.0, kr_s = 0.0, kr_q = 0.0;
    for (int it = lane; it < 384; it += 32) {
        int c = it / 48, i = it - (it/48)*48;
        qr_s += (double)g_SqTot[g][c][i] * (double)Rq[it];
        kr_s += (double)g_SkTot[g][c][i] * (double)Rk[it];
    }
    for (int it = lane; it < 1728; it += 32) {
        int p = it / 48, i = it - (it/48)*48;
        int c, c2; pair_cc(p, c, c2);
        double ww = (c == c2) ? 1.0 : 2.0;
        qr_q += ww * (double)g_PqTot[g][p][i] * (double)ERq[it];
        kr_q += ww * (double)g_PkTot[g][p][i] * (double)ERk[it];
    }
#pragma unroll
    for (int off = 16; off; off >>= 1) {
        qr_s += __shfl_xor_sync(0xffffffffu, qr_s, off);
        qr_q += __shfl_xor_sync(0xffffffffu, qr_q, off);
        kr_s += __shfl_xor_sync(0xffffffffu, kr_s, off);
        kr_q += __shfl_xor_sync(0xffffffffu, kr_q, off);
    }
    if (lane == 0) {
        warp_out[w][0] = qr_s; warp_out[w][1] = qr_q;
        warp_out[w][2] = kr_s; warp_out[w][3] = kr_q;
    }
    __syncthreads();
    if (tid < 8) {
        int gg = tid;
        double N = (double)B2304 * 48.0 * 48.0;
        double fq = (double)(*fqr), fk = (double)(*fkr);

        double m0 = g_qkstat[gg][0] / N;
        double v0 = g_qkstat[gg][1] / N - m0 * m0;
        double m1 = fq * warp_out[gg][0] / N;
        double v1 = fq * fq * warp_out[gg][1] / N - m1 * m1;
        double m2 = fk * warp_out[gg][2] / N;
        double v2 = fk * fk * warp_out[gg][3] / N - m2 * m2;

        double i0 = 1.0 / sqrt(v0 + (double)EPS);
        double i1 = 1.0 / sqrt(v1 + (double)EPS);
        double i2 = 1.0 / sqrt(v2 + (double)EPS);

        double a0 = (double)gsim[0*G8 + gg] * i0;
        double a1 = (double)gsim[1*G8 + gg] * i1;
        double a2 = (double)gsim[2*G8 + gg] * i2;
        double shift = (double)bsim[0*G8+gg] - a0*m0
                     + (double)bsim[1*G8+gg] - a1*m1
                     + (double)bsim[2*G8+gg] - a2*m2;
        g_simco[gg*4+0] = (float)a0;
        g_simco[gg*4+1] = (float)(a1 * fq);
        g_simco[gg*4+2] = (float)(a2 * fk);
        g_simco[gg*4+3] = (float)shift;
    }
}

// ---------------- attention: logits -> softmax -> sv/sve (+ out stats) ----------------
#define AT_SMEM ((6528 + 6528 + 13056 + 48*49 + 8*RELW + 8*RELW + 16*RELW) * 4)
__global__ __launch_bounds__(256)
void k_attn(const float* __restrict__ rel,
            const float* __restrict__ fsv, const float* __restrict__ fsve) {
    extern __shared__ float sm[];
    float* Qs   = sm;                    // 6528
    float* Ks   = Qs + 6528;             // 6528
    float* Vs   = Ks + 6528;             // 16*48*17 = 13056
    float* sim  = Vs + 13056;            // 48*49
    float* relq = sim + 48*49;           // 760
    float* relk = relq + 8*RELW;         // 760
    float* relv = relk + 8*RELW;         // 1520
    __shared__ double red[64];

    int tid = threadIdx.x;
    int g   = blockIdx.y;
    int b0  = blockIdx.x * 16;

    for (int i = tid; i < 32*RELW; i += 256) {
        if      (i <  8*RELW) relq[i]            = rel[i];
        else if (i < 16*RELW) relk[i -  8*RELW]  = rel[i];
        else                  relv[i - 16*RELW]  = rel[i];
    }
    for (int idx = tid; idx < 384*16; idx += 256) {
        int row = idx >> 4, bl = idx & 15;
        int c = row / 48;
        int oq = 192 + g*8 + c;
        int ok = g*24 + c;
        Qs[row*17 + bl] = g_pa[oq] * g_Q [(g*384 + row) * B2304 + b0 + bl] + g_pb[oq];
        Ks[row*17 + bl] = g_pa[ok] * g_Kb[(g*384 + row) * B2304 + b0 + bl] + g_pb[ok];
    }
    for (int idx = tid; idx < 768*16; idx += 256) {
        int row = idx >> 4, bl = idx & 15;
        int c = row / 48;
        int ov = g*24 + 8 + c;
        Vs[row*17 + bl] = g_pa[ov] * g_Vb[(g*768 + row) * B2304 + b0 + bl] + g_pb[ov];
    }
    for (int i = tid; i < 64; i += 256) red[i] = 0.0;
    __syncthreads();

    float A0 = g_simco[g*4+0], A1 = g_simco[g*4+1];
    float A2 = g_simco[g*4+2], SH = g_simco[g*4+3];
    float vsv = *fsv, vsve = *fsve;

    // logits tiling: 16x16 thread grid, each thread a 3x3 (i,j) tile
    int ti = tid >> 4, tj = tid & 15;
    int i0 = ti * 3, j0 = tj * 3;
    int dbq = i0 - j0 + 45;   // relq window base (index 0 -> d-2)
    int dbk = j0 - i0 + 45;

    // sv mapping: 192 threads, thread owns (i, 4 channels)
    int sv_i = tid % 48;
    int sv_c0 = (tid / 48) * 4;

    float lsv_s[4]  = {0,0,0,0}, lsv_q[4]  = {0,0,0,0};
    float lsve_s[4] = {0,0,0,0}, lsve_q[4] = {0,0,0,0};

    for (int bl = 0; bl < 16; bl++) {
        // ---- logits (register tiled) ----
        float aqk[3][3] = {}, aqr[3][3] = {}, akr[3][3] = {};
#pragma unroll 2
        for (int c = 0; c < 8; c++) {
            float qv[3], kv[3], rq[5], rk[5];
#pragma unroll
            for (int r = 0; r < 3; r++) qv[r] = Qs[(c*48 + i0 + r)*17 + bl];
#pragma unroll
            for (int s2 = 0; s2 < 3; s2++) kv[s2] = Ks[(c*48 + j0 + s2)*17 + bl];
#pragma unroll
            for (int t = 0; t < 5; t++) rq[t] = relq[c*RELW + dbq + t];
#pragma unroll
            for (int t = 0; t < 5; t++) rk[t] = relk[c*RELW + dbk + t];
#pragma unroll
            for (int r = 0; r < 3; r++)
#pragma unroll
                for (int s2 = 0; s2 < 3; s2++) {
                    aqk[r][s2] = fmaf(qv[r], kv[s2],        aqk[r][s2]);
                    aqr[r][s2] = fmaf(qv[r], rq[r - s2 + 2], aqr[r][s2]);
                    akr[r][s2] = fmaf(kv[s2], rk[s2 - r + 2], akr[r][s2]);
                }
        }
#pragma unroll
        for (int r = 0; r < 3; r++)
#pragma unroll
            for (int s2 = 0; s2 < 3; s2++)
                sim[(i0 + r)*49 + j0 + s2] =
                    A0*aqk[r][s2] + A1*aqr[r][s2] + A2*akr[r][s2] + SH;
        __syncthreads();

        // ---- softmax: 4 threads per row ----
        if (tid < 192) {
            int row = tid >> 2, q4 = tid & 3;
            float* sr = &sim[row*49];
            float m = -1e30f;
            float e[12];
#pragma unroll
            for (int t = 0; t < 12; t++) m = fmaxf(m, sr[q4 + t*4]);
            m = fmaxf(m, __shfl_xor_sync(0xffffffffu, m, 1));
            m = fmaxf(m, __shfl_xor_sync(0xffffffffu, m, 2));
            float ssum = 0.f;
#pragma unroll
            for (int t = 0; t < 12; t++) {
                e[t] = __expf(sr[q4 + t*4] - m);
                ssum += e[t];
            }
            ssum += __shfl_xor_sync(0xffffffffu, ssum, 1);
            ssum += __shfl_xor_sync(0xffffffffu, ssum, 2);
            float rinv = 1.f / ssum;
#pragma unroll
            for (int t = 0; t < 12; t++) sr[q4 + t*4] = e[t] * rinv;
        }
        __syncthreads();

        // ---- sv / sve ----
        if (tid < 192) {
            float sv[4] = {0,0,0,0}, sve[4] = {0,0,0,0};
            int i = sv_i;
#pragma unroll 4
            for (int j = 0; j < 48; j++) {
                float sj = sim[i*49 + j];
                int d = i - j + 47;
#pragma unroll
                for (int cc = 0; cc < 4; cc++) {
                    int c = sv_c0 + cc;
                    sv[cc]  = fmaf(sj, Vs[(c*48 + j)*17 + bl], sv[cc]);
                    sve[cc] = fmaf(sj, relv[c*RELW + d],        sve[cc]);
                }
            }
            int b = b0 + bl;
#pragma unroll
            for (int cc = 0; cc < 4; cc++) {
                int c = sv_c0 + cc;
                float a  = sv[cc]  * vsv;
                float bb = sve[cc] * vsve;
                g_SV [b*6144 + g*768 + c*48 + i] = a;
                g_SVE[b*6144 + g*768 + c*48 + i] = bb;
                lsv_s[cc]  += a;  lsv_q[cc]  += a*a;
                lsve_s[cc] += bb; lsve_q[cc] += bb*bb;
            }
        }
        __syncthreads();
    }

    if (tid < 192) {
#pragma unroll
        for (int cc = 0; cc < 4; cc++) {
            int c = sv_c0 + cc;
            atomicAdd(&red[c*4+0], (double)lsv_s[cc]);
            atomicAdd(&red[c*4+1], (double)lsv_q[cc]);
            atomicAdd(&red[c*4+2], (double)lsve_s[cc]);
            atomicAdd(&red[c*4+3], (double)lsve_q[cc]);
        }
    }
    __syncthreads();
    if (tid < 16) {
        int o_sv  = (g*16 + tid)*2;
        int o_sve = o_sv + 1;
        atomicAdd(&g_outstats[o_sv*2+0],  red[tid*4+0]);
        atomicAdd(&g_outstats[o_sv*2+1],  red[tid*4+1]);
        atomicAdd(&g_outstats[o_sve*2+0], red[tid*4+2]);
        atomicAdd(&g_outstats[o_sve*2+1], red[tid*4+3]);
    }
}

// ---------------- out BN coefficients ----------------
__global__ void k_outco(const float* __restrict__ gout, const float* __restrict__ bout) {
    int o = threadIdx.x;    // 256
    double N = (double)P110592;
    double s1 = g_outstats[2*o], s2 = g_outstats[2*o+1];
    double mean = s1 / N, var = s2 / N - mean * mean;
    float inv = rsqrtf((float)var + EPS);
    float A = gout[o] * inv;
    g_oA[o] = A;
    g_oC[o] = bout[o] - A * (float)mean;
}

// ---------------- final: affine-combine + transpose [b][r] -> [r][b] ----------------
__global__ __launch_bounds__(256)
void k_final(float* __restrict__ out) {
    __shared__ float tile[32][33];
    int r0 = blockIdx.x * 32;
    int b0 = blockIdx.y * 32;
    int tx = threadIdx.x, ty = threadIdx.y;   // (32, 8)

    int r = r0 + tx;
    int gc = r / 48;
    float Asv  = g_oA[gc*2],   Csv  = g_oC[gc*2];
    float Asve = g_oA[gc*2+1], Csve = g_oC[gc*2+1];
#pragma unroll
    for (int k = 0; k < 4; k++) {
        int b = b0 + ty + k*8;
        float v = Asv * g_SV[b*6144 + r] + Csv
                + Asve * g_SVE[b*6144 + r] + Csve;
        tile[ty + k*8][tx] = v;
    }
    __syncthreads();
#pragma unroll
    for (int k = 0; k < 4; k++) {
        int rr = r0 + ty + k*8;
        out[rr * B2304 + b0 + tx] = tile[tx][ty + k*8];
    }
}

// ---------------- launch ----------------
extern "C" void kernel_launch(void* const* d_in, const int* in_sizes, int n_in,
                              void* d_out, int out_size) {
    const float* x    = (const float*)d_in[0];
    const float* Wkv  = (const float*)d_in[1];
    const float* Wq   = (const float*)d_in[2];
    const float* gkv  = (const float*)d_in[3];
    const float* bkv  = (const float*)d_in[4];
    const float* gq   = (const float*)d_in[5];
    const float* bq   = (const float*)d_in[6];
    const float* gsim = (const float*)d_in[7];
    const float* bsim = (const float*)d_in[8];
    const float* gout = (const float*)d_in[9];
    const float* bout = (const float*)d_in[10];
    const float* rel  = (const float*)d_in[11];
    const float* fqr  = (const float*)d_in[12];
    const float* fkr  = (const float*)d_in[13];
    const float* fsv  = (const float*)d_in[14];
    const float* fsve = (const float*)d_in[15];
    float* out = (float*)d_out;

    cudaFuncSetAttribute(k_proj,  cudaFuncAttributeMaxDynamicSharedMemorySize, 65536);
    cudaFuncSetAttribute(k_stats, cudaFuncAttributeMaxDynamicSharedMemorySize, ST_SMEM);
    cudaFuncSetAttribute(k_attn,  cudaFuncAttributeMaxDynamicSharedMemorySize, AT_SMEM);

    k_zero<<<132, 256>>>();
    k_proj<<<P110592/256, 256, 65536>>>(x, Wkv, Wq);
    k_paffine<<<1, 256>>>(gkv, bkv, gq, bq);
    k_stats<<<dim3(B2304/16, G8), 256, ST_SMEM>>>();
    k_simfin<<<1, 256>>>(rel, gsim, bsim, fqr, fkr);
    k_attn<<<dim3(B2304/16, G8), 256, AT_SMEM>>>(rel, fsv, fsve);
    k_outco<<<1, 256>>>(gout, bout);
    k_final<<<dim3(6144/32, B2304/32), dim3(32, 8)>>>(out);
}

// round 4
// speedup vs baseline: 1.8081x; 1.3526x over previous
#include <cuda_runtime.h>

// ---------------- problem constants ----------------
#define G8      8
#define DK8     8
#define DV16    16
#define CIN64   64
#define H48     48
#define B2304   2304
#define P110592 110592      // B * H
#define NOUT    256         // 192 kv rows + 64 q rows
#define RELW    95          // 2K-1
#define EPS     1e-5f

// ---------------- scratch (device globals; no allocation allowed) ----------------
__device__ float  g_Q  [G8*DK8*H48*B2304];   // [(g*8+c)*48+h][b]  raw projection
__device__ float  g_Kb [G8*DK8*H48*B2304];
__device__ float  g_Vb [G8*DV16*H48*B2304];
__device__ float  g_SV [B2304*G8*DV16*H48];  // [b][(g*16+c)*48+i]
__device__ float  g_SVE[B2304*G8*DV16*H48];
__device__ double g_projstats[NOUT*2];
__device__ float  g_pa[NOUT], g_pb[NOUT];
__device__ float  g_simco[G8*4];             // a_qk, a_qr(*f_qr), a_kr(*f_kr), shift
__device__ double g_outstats[NOUT*2];
__device__ float  g_oA[NOUT], g_oC[NOUT];

// analytic sim-stats accumulators
__device__ float  g_SqTot[G8][8][48];        // sum_b q[b,c,i]
__device__ float  g_SkTot[G8][8][48];
__device__ float  g_PqTot[G8][36][48];       // sum_b q[b,c,i]*q[b,c',i]  (c<=c')
__device__ float  g_PkTot[G8][36][48];
__device__ double g_qkstat[G8][2];           // sum qk, sum qk^2

__device__ __forceinline__ void pair_cc(int p, int& c, int& c2) {
    int base = 0, cc = 0;
#pragma unroll
    for (int r = 0; r < 8; r++) {
        int cnt = 8 - r;
        if (p < base + cnt) { cc = r; break; }
        base += cnt;
    }
    c = cc; c2 = cc + (p - base);
}

// ---------------- zero stats ----------------
__global__ void k_zero() {
    int t = blockIdx.x * blockDim.x + threadIdx.x;
    if (t < NOUT*2) g_projstats[t] = 0.0;
    if (t < NOUT*2) g_outstats[t]  = 0.0;
    if (t < G8*2)   ((double*)g_qkstat)[t] = 0.0;
    int total = G8*8*48;
    for (int i = t; i < total; i += gridDim.x * blockDim.x) {
        (&g_SqTot[0][0][0])[i] = 0.f;
        (&g_SkTot[0][0][0])[i] = 0.f;
    }
    int totalp = G8*36*48;
    for (int i = t; i < totalp; i += gridDim.x * blockDim.x) {
        (&g_PqTot[0][0][0])[i] = 0.f;
        (&g_PkTot[0][0][0])[i] = 0.f;
    }
}

// ---------------- projection GEMM: C[256, 110592] = W[256,64] @ X[64,110592] ----------------
// block: 128 o x 128 s.  grid = (110592/128, 2).  thread: 8o x 8s register tile.
#define PJ_SMEM ((64*128 + 64*132 + 256) * 4)
__global__ __launch_bounds__(256, 2)
void k_proj(const float* __restrict__ x,
            const float* __restrict__ Wkv,
            const float* __restrict__ Wq) {
    extern __shared__ float sm[];
    float* Xs = sm;                // [64][128]
    float* Ws = Xs + 64*128;       // [64][132]  (k-major, transposed W)
    float* ss = Ws + 64*132;       // [128][2] block stats

    int tid = threadIdx.x;
    int ts = tid & 15, to = tid >> 4;
    int og = blockIdx.y;                 // o group: 0 or 1
    int s0 = blockIdx.x * 128;
    int h  = s0 / B2304;
    int bb = s0 - h * B2304;

    if (tid < 256) ss[tid] = 0.f;

    // stage X tile: 64 c-rows x 128 s, float4 coalesced
#pragma unroll
    for (int it = 0; it < 8; it++) {
        int i = tid + it * 256;          // 2048 float4s
        int c = i >> 5, q = i & 31;
        float4 v = *(const float4*)(x + c * P110592 + s0 + q * 4);
        *(float4*)(&Xs[c * 128 + q * 4]) = v;
    }
    // stage W tile (transposed to k-major): this og's 128 rows
#pragma unroll
    for (int it = 0; it < 8; it++) {
        int i = tid + it * 256;          // 2048 float4s
        int o_l = i >> 4, q = i & 15;
        int o = og * 128 + o_l;
        float4 w = (o < 192) ? *(const float4*)(Wkv + o * 64 + q * 4)
                             : *(const float4*)(Wq + (o - 192) * 64 + q * 4);
        int k0 = q * 4;
        Ws[(k0 + 0) * 132 + o_l] = w.x;
        Ws[(k0 + 1) * 132 + o_l] = w.y;
        Ws[(k0 + 2) * 132 + o_l] = w.z;
        Ws[(k0 + 3) * 132 + o_l] = w.w;
    }
    __syncthreads();

    float acc[8][8];
#pragma unroll
    for (int a = 0; a < 8; a++)
#pragma unroll
        for (int b = 0; b < 8; b++) acc[a][b] = 0.f;

#pragma unroll 4
    for (int k = 0; k < 64; k++) {
        float4 xa = *(float4*)(&Xs[k * 128 + ts * 8]);
        float4 xb = *(float4*)(&Xs[k * 128 + ts * 8 + 4]);
        float4 wa = *(float4*)(&Ws[k * 132 + to * 8]);
        float4 wb = *(float4*)(&Ws[k * 132 + to * 8 + 4]);
        float xf[8] = {xa.x, xa.y, xa.z, xa.w, xb.x, xb.y, xb.z, xb.w};
        float wf[8] = {wa.x, wa.y, wa.z, wa.w, wb.x, wb.y, wb.z, wb.w};
#pragma unroll
        for (int oo = 0; oo < 8; oo++)
#pragma unroll
            for (int i = 0; i < 8; i++)
                acc[oo][i] = fmaf(wf[oo], xf[i], acc[oo][i]);
    }

    // epilogue: store + stats
#pragma unroll
    for (int oo = 0; oo < 8; oo++) {
        int o = og * 128 + to * 8 + oo;
        float* dst;
        if (o < 192) {
            int g = o / 24, cc = o - g * 24;
            if (cc < 8) dst = &g_Kb[((g*8 + cc)      * H48 + h) * B2304];
            else        dst = &g_Vb[((g*16 + (cc-8)) * H48 + h) * B2304];
        } else {
            dst = &g_Q[((o - 192) * H48 + h) * B2304];
        }
        float4 v0 = make_float4(acc[oo][0], acc[oo][1], acc[oo][2], acc[oo][3]);
        float4 v1 = make_float4(acc[oo][4], acc[oo][5], acc[oo][6], acc[oo][7]);
        *(float4*)(dst + bb + ts * 8)     = v0;
        *(float4*)(dst + bb + ts * 8 + 4) = v1;

        float s1 = 0.f, s2 = 0.f;
#pragma unroll
        for (int i = 0; i < 8; i++) { s1 += acc[oo][i]; s2 = fmaf(acc[oo][i], acc[oo][i], s2); }
#pragma unroll
        for (int off = 1; off < 16; off <<= 1) {
            s1 += __shfl_xor_sync(0xffffffffu, s1, off);
            s2 += __shfl_xor_sync(0xffffffffu, s2, off);
        }
        if (ts == 0) {
            atomicAdd(&ss[(to * 8 + oo) * 2],     s1);
            atomicAdd(&ss[(to * 8 + oo) * 2 + 1], s2);
        }
    }
    __syncthreads();
    if (tid < 128) {
        int o = og * 128 + tid;
        atomicAdd(&g_projstats[2*o],   (double)ss[tid*2]);
        atomicAdd(&g_projstats[2*o+1], (double)ss[tid*2+1]);
    }
}

// ---------------- fold projection BN into affine ----------------
__global__ void k_paffine(const float* __restrict__ gkv, const float* __restrict__ bkv,
                          const float* __restrict__ gq,  const float* __restrict__ bq) {
    int o = threadIdx.x;   // 256
    double s1 = g_projstats[2*o], s2 = g_projstats[2*o+1];
    double mean = s1 / (double)P110592;
    double var  = s2 / (double)P110592 - mean * mean;
    float inv = rsqrtf((float)var + EPS);
    float gg, bb;
    if (o < 192) { gg = gkv[o]; bb = bkv[o]; }
    else         { gg = gq[o-192]; bb = bq[o-192]; }
    float a = gg * inv;
    g_pa[o] = a;
    g_pb[o] = bb - a * (float)mean;
}

// ---------------- analytic sim stats: moments of post-BN q/k ----------------
#define ST_SMEM ((6528 + 6528) * 4)
__global__ __launch_bounds__(256)
void k_stats() {
    extern __shared__ float sm[];
    float* Qs = sm;                 // 8*48*17 = 6528
    float* Ks = Qs + 6528;          // 6528
    __shared__ double sred[2];

    int tid = threadIdx.x;
    int g   = blockIdx.y;
    int b0  = blockIdx.x * 16;

    // vectorized staged loads: 384 rows x 4 float4 quads per array
#pragma unroll
    for (int it = 0; it < 6; it++) {
        int idx = tid + it * 256;        // < 1536
        int row = idx >> 2, q = idx & 3;
        int c = row / 48;
        int oq = 192 + g*8 + c;
        int ok = g*24 + c;
        float4 vq = *(const float4*)(&g_Q [(g*384 + row) * B2304 + b0 + q*4]);
        float4 vk = *(const float4*)(&g_Kb[(g*384 + row) * B2304 + b0 + q*4]);
        float aq = g_pa[oq], bq = g_pb[oq];
        float ak = g_pa[ok], bk = g_pb[ok];
        float* qd = &Qs[row*17 + q*4];
        float* kd = &Ks[row*17 + q*4];
        qd[0] = fmaf(aq, vq.x, bq); qd[1] = fmaf(aq, vq.y, bq);
        qd[2] = fmaf(aq, vq.z, bq); qd[3] = fmaf(aq, vq.w, bq);
        kd[0] = fmaf(ak, vk.x, bk); kd[1] = fmaf(ak, vk.y, bk);
        kd[2] = fmaf(ak, vk.z, bk); kd[3] = fmaf(ak, vk.w, bk);
    }
    if (tid < 2) sred[tid] = 0.0;
    __syncthreads();

    // qk scalars: per-b Gram pairing + rowsum products
    float lsum = 0.f, lsq = 0.f;
    for (int item = tid; item < 576; item += 256) {        // (pair, bl)
        int p = item >> 4, bl = item & 15;
        int c, c2; pair_cc(p, c, c2);
        float gq = 0.f, gk = 0.f;
#pragma unroll 8
        for (int i = 0; i < 48; i++) {
            gq = fmaf(Qs[(c*48+i)*17+bl], Qs[(c2*48+i)*17+bl], gq);
            gk = fmaf(Ks[(c*48+i)*17+bl], Ks[(c2*48+i)*17+bl], gk);
        }
        float w = (c == c2) ? 1.f : 2.f;
        lsq = fmaf(w * gq, gk, lsq);
    }
    for (int item = tid; item < 128; item += 256) {        // (c, bl)
        int c = item >> 4, bl = item & 15;
        float rq = 0.f, rk = 0.f;
#pragma unroll 8
        for (int i = 0; i < 48; i++) {
            rq += Qs[(c*48+i)*17+bl];
            rk += Ks[(c*48+i)*17+bl];
        }
        lsum = fmaf(rq, rk, lsum);
    }
    atomicAdd(&sred[0], (double)lsum);
    atomicAdd(&sred[1], (double)lsq);

    // per-position first moments
    for (int item = tid; item < 384; item += 256) {
        int c = item / 48, i = item - (item/48)*48;
        float sq = 0.f, sk = 0.f;
#pragma unroll
        for (int bl = 0; bl < 16; bl++) {
            sq += Qs[(c*48+i)*17+bl];
            sk += Ks[(c*48+i)*17+bl];
        }
        atomicAdd(&g_SqTot[g][c][i], sq);
        atomicAdd(&g_SkTot[g][c][i], sk);
    }
    // per-position second cross-moments
    for (int item = tid; item < 1728; item += 256) {
        int p = item / 48, i = item - (item/48)*48;
        int c, c2; pair_cc(p, c, c2);
        float sq = 0.f, sk = 0.f;
#pragma unroll
        for (int bl = 0; bl < 16; bl++) {
            sq = fmaf(Qs[(c*48+i)*17+bl], Qs[(c2*48+i)*17+bl], sq);
            sk = fmaf(Ks[(c*48+i)*17+bl], Ks[(c2*48+i)*17+bl], sk);
        }
        atomicAdd(&g_PqTot[g][p][i], sq);
        atomicAdd(&g_PkTot[g][p][i], sk);
    }
    __syncthreads();
    if (tid == 0) {
        atomicAdd(&g_qkstat[g][0], sred[0]);
        atomicAdd(&g_qkstat[g][1], sred[1]);
    }
}

// ---------------- finalize sim BN coefficients ----------------
__global__ __launch_bounds__(256)
void k_simfin(const float* __restrict__ rel,
              const float* __restrict__ gsim, const float* __restrict__ bsim,
              const float* __restrict__ fqr,  const float* __restrict__ fkr) {
    __shared__ float relq_s[8*RELW], relk_s[8*RELW];
    __shared__ float Rq[384], Rk[384];
    __shared__ float ERq[1728], ERk[1728];
    __shared__ double warp_out[8][4];

    int tid = threadIdx.x;
    for (int i = tid; i < 16*RELW; i += 256) {
        if (i < 8*RELW) relq_s[i] = rel[i];
        else            relk_s[i - 8*RELW] = rel[i];
    }
    __syncthreads();

    for (int it = tid; it < 384; it += 256) {
        int c = it / 48, i = it - (it/48)*48;
        float s = 0.f, sk = 0.f;
#pragma unroll 8
        for (int d = 0; d < 48; d++) {
            s  += relq_s[c*RELW + i + d];
            sk += relk_s[c*RELW + i + d];
        }
        Rq[it] = s; Rk[it] = sk;
    }
    for (int it = tid; it < 1728; it += 256) {
        int p = it / 48, i = it - (it/48)*48;
        int c, c2; pair_cc(p, c, c2);
        float s = 0.f, sk = 0.f;
#pragma unroll 8
        for (int d = 0; d < 48; d++) {
            s  = fmaf(relq_s[c*RELW + i + d], relq_s[c2*RELW + i + d], s);
            sk = fmaf(relk_s[c*RELW + i + d], relk_s[c2*RELW + i + d], sk);
        }
        ERq[it] = s; ERk[it] = sk;
    }
    __syncthreads();

    int w = tid >> 5, lane = tid & 31;   // warp w handles group g = w
    int g = w;
    double qr_s = 0.0, qr_q = 0.0, kr_s = 0.0, kr_q = 0.0;
    for (int it = lane; it < 384; it += 32) {
        int c = it / 48, i = it - (it/48)*48;
        qr_s += (double)g_SqTot[g][c][i] * (double)Rq[it];
        kr_s += (double)g_SkTot[g][c][i] * (double)Rk[it];
    }
    for (int it = lane; it < 1728; it += 32) {
        int p = it / 48, i = it - (it/48)*48;
        int c, c2; pair_cc(p, c, c2);
        double ww = (c == c2) ? 1.0 : 2.0;
        qr_q += ww * (double)g_PqTot[g][p][i] * (double)ERq[it];
        kr_q += ww * (double)g_PkTot[g][p][i] * (double)ERk[it];
    }
#pragma unroll
    for (int off = 16; off; off >>= 1) {
        qr_s += __shfl_xor_sync(0xffffffffu, qr_s, off);
        qr_q += __shfl_xor_sync(0xffffffffu, qr_q, off);
        kr_s += __shfl_xor_sync(0xffffffffu, kr_s, off);
        kr_q += __shfl_xor_sync(0xffffffffu, kr_q, off);
    }
    if (lane == 0) {
        warp_out[w][0] = qr_s; warp_out[w][1] = qr_q;
        warp_out[w][2] = kr_s; warp_out[w][3] = kr_q;
    }
    __syncthreads();
    if (tid < 8) {
        int gg = tid;
        double N = (double)B2304 * 48.0 * 48.0;
        double fq = (double)(*fqr), fk = (double)(*fkr);

        double m0 = g_qkstat[gg][0] / N;
        double v0 = g_qkstat[gg][1] / N - m0 * m0;
        double m1 = fq * warp_out[gg][0] / N;
        double v1 = fq * fq * warp_out[gg][1] / N - m1 * m1;
        double m2 = fk * warp_out[gg][2] / N;
        double v2 = fk * fk * warp_out[gg][3] / N - m2 * m2;

        double i0 = 1.0 / sqrt(v0 + (double)EPS);
        double i1 = 1.0 / sqrt(v1 + (double)EPS);
        double i2 = 1.0 / sqrt(v2 + (double)EPS);

        double a0 = (double)gsim[0*G8 + gg] * i0;
        double a1 = (double)gsim[1*G8 + gg] * i1;
        double a2 = (double)gsim[2*G8 + gg] * i2;
        double shift = (double)bsim[0*G8+gg] - a0*m0
                     + (double)bsim[1*G8+gg] - a1*m1
                     + (double)bsim[2*G8+gg] - a2*m2;
        g_simco[gg*4+0] = (float)a0;
        g_simco[gg*4+1] = (float)(a1 * fq);
        g_simco[gg*4+2] = (float)(a2 * fk);
        g_simco[gg*4+3] = (float)shift;
    }
}

// ---------------- attention: logits -> softmax -> sv/sve (+ out stats) ----------------
#define AT_SMEM ((6528 + 6528 + 13056 + 48*49 + 8*RELW + 8*RELW + 16*RELW) * 4)
__global__ __launch_bounds__(256)
void k_attn(const float* __restrict__ rel,
            const float* __restrict__ fsv, const float* __restrict__ fsve) {
    extern __shared__ float sm[];
    float* Qs   = sm;                    // 6528
    float* Ks   = Qs + 6528;             // 6528
    float* Vs   = Ks + 6528;             // 16*48*17 = 13056
    float* sim  = Vs + 13056;            // 48*49
    float* relq = sim + 48*49;           // 760
    float* relk = relq + 8*RELW;         // 760
    float* relv = relk + 8*RELW;         // 1520
    __shared__ double red[64];

    int tid = threadIdx.x;
    int g   = blockIdx.y;
    int b0  = blockIdx.x * 16;

    for (int i = tid; i < 32*RELW; i += 256) {
        if      (i <  8*RELW) relq[i]            = rel[i];
        else if (i < 16*RELW) relk[i -  8*RELW]  = rel[i];
        else                  relv[i - 16*RELW]  = rel[i];
    }
    // vectorized Q/K staging: 384 rows x 4 quads
#pragma unroll
    for (int it = 0; it < 6; it++) {
        int idx = tid + it * 256;
        int row = idx >> 2, q = idx & 3;
        int c = row / 48;
        int oq = 192 + g*8 + c;
        int ok = g*24 + c;
        float4 vq = *(const float4*)(&g_Q [(g*384 + row) * B2304 + b0 + q*4]);
        float4 vk = *(const float4*)(&g_Kb[(g*384 + row) * B2304 + b0 + q*4]);
        float aq = g_pa[oq], bq = g_pb[oq];
        float ak = g_pa[ok], bk = g_pb[ok];
        float* qd = &Qs[row*17 + q*4];
        float* kd = &Ks[row*17 + q*4];
        qd[0] = fmaf(aq, vq.x, bq); qd[1] = fmaf(aq, vq.y, bq);
        qd[2] = fmaf(aq, vq.z, bq); qd[3] = fmaf(aq, vq.w, bq);
        kd[0] = fmaf(ak, vk.x, bk); kd[1] = fmaf(ak, vk.y, bk);
        kd[2] = fmaf(ak, vk.z, bk); kd[3] = fmaf(ak, vk.w, bk);
    }
    // vectorized V staging: 768 rows x 4 quads
#pragma unroll
    for (int it = 0; it < 12; it++) {
        int idx = tid + it * 256;
        int row = idx >> 2, q = idx & 3;
        int c = row / 48;
        int ov = g*24 + 8 + c;
        float4 vv = *(const float4*)(&g_Vb[(g*768 + row) * B2304 + b0 + q*4]);
        float av = g_pa[ov], bv = g_pb[ov];
        float* vd = &Vs[row*17 + q*4];
        vd[0] = fmaf(av, vv.x, bv); vd[1] = fmaf(av, vv.y, bv);
        vd[2] = fmaf(av, vv.z, bv); vd[3] = fmaf(av, vv.w, bv);
    }
    for (int i = tid; i < 64; i += 256) red[i] = 0.0;
    __syncthreads();

    float A0 = g_simco[g*4+0], A1 = g_simco[g*4+1];
    float A2 = g_simco[g*4+2], SH = g_simco[g*4+3];
    float vsv = *fsv, vsve = *fsve;

    int ti = tid >> 4, tj = tid & 15;
    int i0 = ti * 3, j0 = tj * 3;
    int dbq = i0 - j0 + 45;
    int dbk = j0 - i0 + 45;

    int sv_i = tid % 48;
    int sv_c0 = (tid / 48) * 4;

    float lsv_s[4]  = {0,0,0,0}, lsv_q[4]  = {0,0,0,0};
    float lsve_s[4] = {0,0,0,0}, lsve_q[4] = {0,0,0,0};

    for (int bl = 0; bl < 16; bl++) {
        float aqk[3][3] = {}, aqr[3][3] = {}, akr[3][3] = {};
#pragma unroll 2
        for (int c = 0; c < 8; c++) {
            float qv[3], kv[3], rq[5], rk[5];
#pragma unroll
            for (int r = 0; r < 3; r++) qv[r] = Qs[(c*48 + i0 + r)*17 + bl];
#pragma unroll
            for (int s2 = 0; s2 < 3; s2++) kv[s2] = Ks[(c*48 + j0 + s2)*17 + bl];
#pragma unroll
            for (int t = 0; t < 5; t++) rq[t] = relq[c*RELW + dbq + t];
#pragma unroll
            for (int t = 0; t < 5; t++) rk[t] = relk[c*RELW + dbk + t];
#pragma unroll
            for (int r = 0; r < 3; r++)
#pragma unroll
                for (int s2 = 0; s2 < 3; s2++) {
                    aqk[r][s2] = fmaf(qv[r], kv[s2],         aqk[r][s2]);
                    aqr[r][s2] = fmaf(qv[r], rq[r - s2 + 2], aqr[r][s2]);
                    akr[r][s2] = fmaf(kv[s2], rk[s2 - r + 2], akr[r][s2]);
                }
        }
#pragma unroll
        for (int r = 0; r < 3; r++)
#pragma unroll
            for (int s2 = 0; s2 < 3; s2++)
                sim[(i0 + r)*49 + j0 + s2] =
                    A0*aqk[r][s2] + A1*aqr[r][s2] + A2*akr[r][s2] + SH;
        __syncthreads();

        if (tid < 192) {
            int row = tid >> 2, q4 = tid & 3;
            float* sr = &sim[row*49];
            float m = -1e30f;
            float e[12];
#pragma unroll
            for (int t = 0; t < 12; t++) m = fmaxf(m, sr[q4 + t*4]);
            m = fmaxf(m, __shfl_xor_sync(0xffffffffu, m, 1));
            m = fmaxf(m, __shfl_xor_sync(0xffffffffu, m, 2));
            float ssum = 0.f;
#pragma unroll
            for (int t = 0; t < 12; t++) {
                e[t] = __expf(sr[q4 + t*4] - m);
                ssum += e[t];
            }
            ssum += __shfl_xor_sync(0xffffffffu, ssum, 1);
            ssum += __shfl_xor_sync(0xffffffffu, ssum, 2);
            float rinv = 1.f / ssum;
#pragma unroll
            for (int t = 0; t < 12; t++) sr[q4 + t*4] = e[t] * rinv;
        }
        __syncthreads();

        if (tid < 192) {
            float sv[4] = {0,0,0,0}, sve[4] = {0,0,0,0};
            int i = sv_i;
#pragma unroll 4
            for (int j = 0; j < 48; j++) {
                float sj = sim[i*49 + j];
                int d = i - j + 47;
#pragma unroll
                for (int cc = 0; cc < 4; cc++) {
                    int c = sv_c0 + cc;
                    sv[cc]  = fmaf(sj, Vs[(c*48 + j)*17 + bl], sv[cc]);
                    sve[cc] = fmaf(sj, relv[c*RELW + d],        sve[cc]);
                }
            }
            int b = b0 + bl;
#pragma unroll
            for (int cc = 0; cc < 4; cc++) {
                int c = sv_c0 + cc;
                float a  = sv[cc]  * vsv;
                float bb = sve[cc] * vsve;
                g_SV [b*6144 + g*768 + c*48 + i] = a;
                g_SVE[b*6144 + g*768 + c*48 + i] = bb;
                lsv_s[cc]  += a;  lsv_q[cc]  += a*a;
                lsve_s[cc] += bb; lsve_q[cc] += bb*bb;
            }
        }
        __syncthreads();
    }

    if (tid < 192) {
#pragma unroll
        for (int cc = 0; cc < 4; cc++) {
            int c = sv_c0 + cc;
            atomicAdd(&red[c*4+0], (double)lsv_s[cc]);
            atomicAdd(&red[c*4+1], (double)lsv_q[cc]);
            atomicAdd(&red[c*4+2], (double)lsve_s[cc]);
            atomicAdd(&red[c*4+3], (double)lsve_q[cc]);
        }
    }
    __syncthreads();
    if (tid < 16) {
        int o_sv  = (g*16 + tid)*2;
        int o_sve = o_sv + 1;
        atomicAdd(&g_outstats[o_sv*2+0],  red[tid*4+0]);
        atomicAdd(&g_outstats[o_sv*2+1],  red[tid*4+1]);
        atomicAdd(&g_outstats[o_sve*2+0], red[tid*4+2]);
        atomicAdd(&g_outstats[o_sve*2+1], red[tid*4+3]);
    }
}

// ---------------- out BN coefficients ----------------
__global__ void k_outco(const float* __restrict__ gout, const float* __restrict__ bout) {
    int o = threadIdx.x;    // 256
    double N = (double)P110592;
    double s1 = g_outstats[2*o], s2 = g_outstats[2*o+1];
    double mean = s1 / N, var = s2 / N - mean * mean;
    float inv = rsqrtf((float)var + EPS);
    float A = gout[o] * inv;
    g_oA[o] = A;
    g_oC[o] = bout[o] - A * (float)mean;
}

// ---------------- final: affine-combine + transpose [b][r] -> [r][b] ----------------
__global__ __launch_bounds__(256)
void k_final(float* __restrict__ out) {
    __shared__ float tile[32][33];
    int r0 = blockIdx.x * 32;
    int b0 = blockIdx.y * 32;
    int tx = threadIdx.x, ty = threadIdx.y;   // (32, 8)

    int r = r0 + tx;
    int gc = r / 48;
    float Asv  = g_oA[gc*2],   Csv  = g_oC[gc*2];
    float Asve = g_oA[gc*2+1], Csve = g_oC[gc*2+1];
#pragma unroll
    for (int k = 0; k < 4; k++) {
        int b = b0 + ty + k*8;
        float v = Asv * g_SV[b*6144 + r] + Csv
                + Asve * g_SVE[b*6144 + r] + Csve;
        tile[ty + k*8][tx] = v;
    }
    __syncthreads();
#pragma unroll
    for (int k = 0; k < 4; k++) {
        int rr = r0 + ty + k*8;
        out[rr * B2304 + b0 + tx] = tile[tx][ty + k*8];
    }
}

// ---------------- launch ----------------
extern "C" void kernel_launch(void* const* d_in, const int* in_sizes, int n_in,
                              void* d_out, int out_size) {
    const float* x    = (const float*)d_in[0];
    const float* Wkv  = (const float*)d_in[1];
    const float* Wq   = (const float*)d_in[2];
    const float* gkv  = (const float*)d_in[3];
    const float* bkv  = (const float*)d_in[4];
    const float* gq   = (const float*)d_in[5];
    const float* bq   = (const float*)d_in[6];
    const float* gsim = (const float*)d_in[7];
    const float* bsim = (const float*)d_in[8];
    const float* gout = (const float*)d_in[9];
    const float* bout = (const float*)d_in[10];
    const float* rel  = (const float*)d_in[11];
    const float* fqr  = (const float*)d_in[12];
    const float* fkr  = (const float*)d_in[13];
    const float* fsv  = (const float*)d_in[14];
    const float* fsve = (const float*)d_in[15];
    float* out = (float*)d_out;

    cudaFuncSetAttribute(k_proj,  cudaFuncAttributeMaxDynamicSharedMemorySize, PJ_SMEM);
    cudaFuncSetAttribute(k_stats, cudaFuncAttributeMaxDynamicSharedMemorySize, ST_SMEM);
    cudaFuncSetAttribute(k_attn,  cudaFuncAttributeMaxDynamicSharedMemorySize, AT_SMEM);

    k_zero<<<132, 256>>>();
    k_proj<<<dim3(P110592/128, 2), 256, PJ_SMEM>>>(x, Wkv, Wq);
    k_paffine<<<1, 256>>>(gkv, bkv, gq, bq);
    k_stats<<<dim3(B2304/16, G8), 256, ST_SMEM>>>();
    k_simfin<<<1, 256>>>(rel, gsim, bsim, fqr, fkr);
    k_attn<<<dim3(B2304/16, G8), 256, AT_SMEM>>>(rel, fsv, fsve);
    k_outco<<<1, 256>>>(gout, bout);
    k_final<<<dim3(6144/32, B2304/32), dim3(32, 8)>>>(out);
}